// round 17
// baseline (speedup 1.0000x reference)
#include <cuda_runtime.h>
#include <cstdint>

#define OMEGA 30.0f
#define HID 128
#define MROW 128          // points per CTA
#define THREADS 512
#define NPTS 2048
#define NCHUNK (NPTS / MROW)
#define HS 130            // hT row stride (words): 130 % 32 = 2
#define WS 288            // WD row stride (words): 8 blocks x 36-word stagger

// smem offsets (floats)
#define HT_OFF   0
#define WD_OFF   (128 * HS)              // 16640
#define CS_OFF   (WD_OFF + 128 * WS)     // 53504
#define BIAS_OFF (CS_OFF + 1024)
#define ZWB_OFF  (BIAS_OFF + 128)
#define W3_OFF   (ZWB_OFF + 128)
#define PART_OFF (W3_OFF + 128)
#define ZSM_OFF  (PART_OFF + 1024)       // part: 512 uint64 = 1024 floats
#define B3_OFF   (ZSM_OFF + 16)
#define SMEM_FLOATS (B3_OFF + 8)
#define SMEM_BYTES  (SMEM_FLOATS * 4)

// monotonic staggered word offset of column c within a WD row:
// block b = c>>4 starts at 36*b; injective, max 282 < WS.
#define WOFF(c) (2 * (c) + 4 * ((c) >> 4))

// ---------------- packed f32x2 helpers ----------------
__device__ __forceinline__ uint64_t pack2(float lo, float hi) {
    uint64_t r;
    asm("mov.b64 %0, {%1, %2};" : "=l"(r) : "f"(lo), "f"(hi));
    return r;
}
__device__ __forceinline__ float2 unpack2(uint64_t v) {
    float2 f;
    asm("mov.b64 {%0, %1}, %2;" : "=f"(f.x), "=f"(f.y) : "l"(v));
    return f;
}
__device__ __forceinline__ uint64_t fma2(uint64_t a, uint64_t b, uint64_t c) {
    uint64_t d;
    asm("fma.rn.f32x2 %0, %1, %2, %3;" : "=l"(d) : "l"(a), "l"(b), "l"(c));
    return d;
}
__device__ __forceinline__ uint64_t add2(uint64_t a, uint64_t b) {
    uint64_t d;
    asm("add.rn.f32x2 %0, %1, %2;" : "=l"(d) : "l"(a), "l"(b));
    return d;
}
#define DUP(c) pack2((c), (c))

// -------- packed sin via exact CW reduction + MUFU poly (both lanes) --------
__device__ __forceinline__ uint64_t sin2(uint64_t x2) {
    uint64_t y2 = fma2(x2, DUP(0.3183098861837907f), DUP(12582912.0f));
    uint64_t sgn = (y2 & 0x0000000100000001ULL) << 31;
    uint64_t k2 = add2(y2, DUP(-12582912.0f));
    uint64_t r2 = fma2(k2, DUP(-3.14159274f), x2);
    r2 = fma2(k2, DUP(8.742277657e-8f), r2);
    r2 ^= sgn;                       // sin(x) = sin((-1)^k r)
    float2 rf = unpack2(r2);
    return pack2(__sinf(rf.x), __sinf(rf.y));
}

// ------ one layer: h' = sin(OMEGA*h@W + biasO), dup-B / pair-A packed -------
// hT[k][pt] scalar per point (stride HS); WD[k][.] weights duplicated (w,w)
// at staggered offsets (stride WS). Thread: point-pairs {pp0, pp0+32} x cols
// col0..col0+7. Each fma2: (h_2p,h_2p+1) * (w_c,w_c) — no register packing.
// PF=1: prefetch + dup-dequant NEXT layer into WD + bias_slot, overlapped
// with writeback. Caller syncs after return.
template<int K, int PF>
__device__ __forceinline__ void layer_gemm_sin(float* hT, float* WD,
                                               const float* biasO,
                                               int pp0, int col0,
                                               const int* nlab,
                                               const float* ncent,
                                               const float* nbias,
                                               float* bias_slot, int tid) {
    uint64_t acc[2][8];
#pragma unroll
    for (int j = 0; j < 2; j++)
#pragma unroll
        for (int t = 0; t < 8; t++) acc[j][t] = 0ULL;

    const float* hp = hT + 2 * pp0;
    const float* wp = WD + WOFF(col0);   // col0..col0+7 stay inside one block
#pragma unroll 4
    for (int k = 0; k < K; k++) {
        uint64_t A0 = *(const uint64_t*)(hp + k * HS);
        uint64_t A1 = *(const uint64_t*)(hp + k * HS + 64);
        ulonglong2 B0 = *(const ulonglong2*)(wp + k * WS);
        ulonglong2 B1 = *(const ulonglong2*)(wp + k * WS + 4);
        ulonglong2 B2 = *(const ulonglong2*)(wp + k * WS + 8);
        ulonglong2 B3 = *(const ulonglong2*)(wp + k * WS + 12);
        uint64_t Bv[8] = {B0.x, B0.y, B1.x, B1.y, B2.x, B2.y, B3.x, B3.y};
#pragma unroll
        for (int t = 0; t < 8; t++) acc[0][t] = fma2(A0, Bv[t], acc[0][t]);
#pragma unroll
        for (int t = 0; t < 8; t++) acc[1][t] = fma2(A1, Bv[t], acc[1][t]);
    }

    // epilogue: x = OMEGA*acc + biasO (pre-scaled), CW+MUFU sin
    const uint64_t om2 = DUP(OMEGA);
#pragma unroll
    for (int t = 0; t < 8; t++) {
        uint64_t bw = DUP(biasO[col0 + t]);
        acc[0][t] = sin2(fma2(om2, acc[0][t], bw));
        acc[1][t] = sin2(fma2(om2, acc[1][t], bw));
    }
    __syncthreads();   // all reads of hT/WD/biasO complete

    // PF: label LDGs early (latency hidden behind writeback)
    int4 lv[2][4];
    float nb = 0.0f;
    if (PF) {
#pragma unroll
        for (int u = 0; u < 2; u++) {
            int unit = tid + 512 * u;
            const int4* lp = (const int4*)(nlab + (unit >> 3) * HID + (unit & 7) * 16);
#pragma unroll
            for (int i = 0; i < 4; i++) lv[u][i] = lp[i];
        }
        if (tid < HID) nb = nbias[tid];
    }

    // writeback: pairs of consecutive points per column
#pragma unroll
    for (int t = 0; t < 8; t++) {
        float* dst = hT + (col0 + t) * HS + 2 * pp0;
        *(uint64_t*)(dst)      = acc[0][t];
        *(uint64_t*)(dst + 64) = acc[1][t];
    }

    if (PF) {
#pragma unroll
        for (int u = 0; u < 2; u++) {
            int unit = tid + 512 * u;
            int k = unit >> 3, blk = unit & 7;
            float* wb = WD + k * WS + 36 * blk;   // block base (staggered)
#pragma unroll
            for (int i = 0; i < 4; i++) {
                int4 v = lv[u][i];
                float w0 = ncent[v.x], w1 = ncent[v.y];
                float w2 = ncent[v.z], w3 = ncent[v.w];
                *(float4*)(wb + i * 8)     = make_float4(w0, w0, w1, w1);
                *(float4*)(wb + i * 8 + 4) = make_float4(w2, w2, w3, w3);
            }
        }
        if (tid < HID) bias_slot[tid] = OMEGA * nb;
    }
}

__global__ void __launch_bounds__(THREADS, 1)
ecnr_kernel(const float* __restrict__ x,
            const int* __restrict__ mlp_idx,
            const int* __restrict__ block_idx,
            const float* __restrict__ latent_table,
            const float* __restrict__ cent0, const int* __restrict__ lab0, const float* __restrict__ bias0,
            const float* __restrict__ cent1, const int* __restrict__ lab1, const float* __restrict__ bias1,
            const float* __restrict__ cent2, const int* __restrict__ lab2, const float* __restrict__ bias2,
            const float* __restrict__ cent3, const int* __restrict__ lab3, const float* __restrict__ bias3,
            float* __restrict__ out) {
    extern __shared__ float sm[];
    float* hT  = sm + HT_OFF;           // [128][HS]
    float* WD  = sm + WD_OFF;           // [128][WS] duplicated weights
    float* cs0 = sm + CS_OFF;
    float* cs1 = cs0 + 256;
    float* cs2 = cs1 + 256;
    float* cs3 = cs2 + 256;
    float* bias_s = sm + BIAS_OFF;      // 128 (OMEGA*bias, layers 1-2)
    float* zwb  = sm + ZWB_OFF;         // 128
    float* w3s  = sm + W3_OFF;          // 128
    float* part = sm + PART_OFF;        // 1024 (512 uint64 pairs)
    float* zsm  = sm + ZSM_OFF;         // 13
    float* b3s  = sm + B3_OFF;          // 1

    int tid = threadIdx.x;
    int b   = blockIdx.y;
    int pt0 = blockIdx.x * MROW;
    int mlp = mlp_idx[b];
    int blk = block_idx[b];

    if (tid < 256) {
        cs0[tid] = cent0[tid];
        cs1[tid] = cent1[tid];
        cs2[tid] = cent2[tid];
        cs3[tid] = cent3[tid];
    }
    if (tid == 0) b3s[0] = bias3[mlp];
    if (tid < 13) zsm[tid] = latent_table[((long)mlp * 8 + blk) * 13 + tid];

    // layer-0 input rows 0..2 (latent folded into zwb)
    if (tid < MROW) {
        const float* xp = x + ((long)b * NPTS + pt0 + tid) * 3;
        hT[0 * HS + tid] = xp[0];
        hT[1 * HS + tid] = xp[1];
        hT[2 * HS + tid] = xp[2];
    }

    // layer-0 labels: thread=column, all 16 k-rows (coalesced per k)
    int v0[16];
    float bia0 = 0.0f;
    if (tid < HID) {
        const int* lp = lab0 + mlp * (16 * HID) + tid;
#pragma unroll
        for (int i = 0; i < 16; i++) v0[i] = lp[i * HID];
        bia0 = bias0[mlp * HID + tid];
    }
    __syncthreads();        // cs0/zsm/hT visible

    // WD rows 0..2 (duplicated), zwb = OMEGA*(z.W[3:16] + b0)
    if (tid < HID) {
        int c = tid;
#pragma unroll
        for (int k = 0; k < 3; k++) {
            float w = cs0[v0[k]];
            *(uint64_t*)(WD + k * WS + WOFF(c)) = pack2(w, w);
        }
        float s = bia0;
#pragma unroll
        for (int j = 0; j < 13; j++)
            s = fmaf(zsm[j], cs0[v0[3 + j]], s);
        zwb[c] = OMEGA * s;
    }
    __syncthreads();

    // tiling: pp0 = wr*8 + lr (point-pairs, +32 for second), col0 = wc*32+lc*8
    int wid = tid >> 5, lane = tid & 31;
    int lr = lane & 7, lc = lane >> 3;
    int wr = wid & 3, wc = wid >> 2;
    int pp0  = wr * 8 + lr;
    int col0 = wc * 32 + lc * 8;

    layer_gemm_sin<3, 1>(hT, WD, zwb, pp0, col0,
                         lab1 + (long)mlp * (HID * HID), cs1,
                         bias1 + mlp * HID, bias_s, tid);
    __syncthreads();

    layer_gemm_sin<128, 1>(hT, WD, bias_s, pp0, col0,
                           lab2 + (long)mlp * (HID * HID), cs2,
                           bias2 + mlp * HID, bias_s, tid);
    __syncthreads();

    layer_gemm_sin<128, 0>(hT, WD, bias_s, pp0, col0,
                           nullptr, nullptr, nullptr, nullptr, tid);

    // layer-3 weights (128x1), scalar
    if (tid < 32) {
        int4 v = ((const int4*)(lab3 + mlp * HID))[tid];
        ((float4*)w3s)[tid] = make_float4(cs3[v.x], cs3[v.y], cs3[v.z], cs3[v.w]);
    }
    __syncthreads();

    // layer 3: packed dot, 8 threads per point-pair (k-eighths)
    {
        int pp = tid >> 3, q = tid & 7;
        uint64_t s2 = 0ULL;
        const float* hp = hT + (q * 16) * HS + 2 * pp;
        const float* wp = w3s + q * 16;
#pragma unroll 8
        for (int i = 0; i < 16; i++)
            s2 = fma2(*(const uint64_t*)(hp + i * HS), DUP(wp[i]), s2);
        ((uint64_t*)part)[q * 64 + pp] = s2;
    }
    __syncthreads();
    if (tid < MROW) {
        float s = b3s[0];
#pragma unroll
        for (int q = 0; q < 8; q++) s += part[q * 128 + tid];
        out[(long)b * NPTS + pt0 + tid] = s;
    }
}

extern "C" void kernel_launch(void* const* d_in, const int* in_sizes, int n_in,
                              void* d_out, int out_size) {
    (void)n_in; (void)out_size;
    cudaFuncSetAttribute(ecnr_kernel,
                         cudaFuncAttributeMaxDynamicSharedMemorySize, SMEM_BYTES);
    int B = in_sizes[1];                 // number of samples (mlp_idx count)
    dim3 grid(NCHUNK, B);
    ecnr_kernel<<<grid, THREADS, SMEM_BYTES>>>(
        (const float*)d_in[0], (const int*)d_in[1], (const int*)d_in[2],
        (const float*)d_in[3],
        (const float*)d_in[4],  (const int*)d_in[5],  (const float*)d_in[6],
        (const float*)d_in[7],  (const int*)d_in[8],  (const float*)d_in[9],
        (const float*)d_in[10], (const int*)d_in[11], (const float*)d_in[12],
        (const float*)d_in[13], (const int*)d_in[14], (const float*)d_in[15],
        (float*)d_out);
}